// round 1
// baseline (speedup 1.0000x reference)
#include <cuda_runtime.h>

// Problem constants
#define GG   8          // groups
#define KK   1024       // codes per group
#define DD   64         // sub-dim
#define BB   16         // batch
#define TS   4000       // time steps
#define CF   512        // C*F = embed dim
#define TT   124        // tokens per CTA tile (124*4B*tile keeps float4 alignment)
#define TILES 33        // ceil(4000/124)
#define KC   64         // codes per smem chunk
#define NTH  256

__device__ float g_e2[GG * KK];

// ---- packed f32x2 helpers (Blackwell FFMA2) ----
__device__ __forceinline__ unsigned long long pack2(float x, float y) {
    unsigned long long r;
    asm("mov.b64 %0, {%1, %2};" : "=l"(r) : "f"(x), "f"(y));
    return r;
}
__device__ __forceinline__ unsigned long long ffma2(unsigned long long a,
                                                    unsigned long long b,
                                                    unsigned long long c) {
    unsigned long long d;
    asm("fma.rn.f32x2 %0, %1, %2, %3;" : "=l"(d) : "l"(a), "l"(b), "l"(c));
    return d;
}
__device__ __forceinline__ float2 unpack2(unsigned long long v) {
    float2 r;
    asm("mov.b64 {%0, %1}, %2;" : "=f"(r.x), "=f"(r.y) : "l"(v));
    return r;
}

// e2[g][k] = sum_d cb[g][k][d]^2, sequential order (deterministic)
__global__ void e2_kernel(const float* __restrict__ cb) {
    int k = blockIdx.x * blockDim.x + threadIdx.x;
    if (k < GG * KK) {
        const float* r = cb + (size_t)k * DD;
        float s = 0.f;
        #pragma unroll
        for (int d = 0; d < DD; ++d) s = fmaf(r[d], r[d], s);
        g_e2[k] = s;
    }
}

__global__ __launch_bounds__(NTH)
void vq_main(const float* __restrict__ x, const float* __restrict__ cb,
             float* __restrict__ out, int two_copies) {
    __shared__ float xs[DD][TT];       // 31744 B, identity layout [d][t]
    __shared__ float es[KC][65];       // 16640 B, pad to 65 floats/row
    // (reduction buffers overlay es after the main loop)

    const int tile = blockIdx.x % TILES;
    int rest = blockIdx.x / TILES;
    const int b = rest % BB;
    const int g = rest / BB;
    const int t0 = tile * TT;
    const int nt = min(TT, TS - t0);
    const int tid = threadIdx.x;

    // ---- load x tile: rows dd=0..63, TT floats each, coalesced ----
    const float* xb = x + ((size_t)(b * CF + g * DD)) * TS + t0;
    if (nt == TT) {
        for (int i = tid; i < DD * (TT / 4); i += NTH) {
            int dd = i / (TT / 4), tq = i % (TT / 4);
            float4 v = *(const float4*)(xb + (size_t)dd * TS + tq * 4);
            *(float4*)&xs[dd][tq * 4] = v;
        }
    } else {
        for (int i = tid; i < DD * TT; i += NTH) {
            int dd = i / TT, tt = i % TT;
            xs[dd][tt] = (tt < nt) ? xb[(size_t)dd * TS + tt] : 0.f;
        }
    }
    __syncthreads();

    const int kg = tid & 7;        // code-slice 0..7
    const int tg = tid >> 3;       // token group 0..31 (31 active: 31*4=124)
    const bool active = (tg < TT / 4);
    const int tb = tg * 4;

    // per-thread x2 for its 4 tokens (sequential d order, matches ref)
    float x2[4];
    if (active) {
        #pragma unroll
        for (int i = 0; i < 4; ++i) {
            float s = 0.f;
            for (int dd = 0; dd < DD; ++dd) {
                float v = xs[dd][tb + i];
                s = fmaf(v, v, s);
            }
            x2[i] = s;
        }
    }

    const float* cbg = cb + (size_t)g * KK * DD;
    const float* e2g = g_e2 + g * KK;

    const float INF = __int_as_float(0x7f800000);
    float best[4] = {INF, INF, INF, INF};
    int bidx[4] = {0, 0, 0, 0};

    for (int c = 0; c < KK / KC; ++c) {   // 16 chunks of 64 codes
        // ---- load code chunk into es[kl][d] (scalar stores; 2-way max conflict) ----
        {
            const float* src = cbg + (size_t)c * KC * DD;
            int kl = tid >> 2;             // 0..63
            int p = tid & 3;               // 0..3
            #pragma unroll
            for (int q = 0; q < 4; ++q) {
                float4 v = *(const float4*)(src + kl * DD + p * 16 + q * 4);
                int d0 = p * 16 + q * 4;
                es[kl][d0 + 0] = v.x;
                es[kl][d0 + 1] = v.y;
                es[kl][d0 + 2] = v.z;
                es[kl][d0 + 3] = v.w;
            }
        }
        __syncthreads();

        if (active) {
            unsigned long long acc[8][2];
            #pragma unroll
            for (int j = 0; j < 8; ++j) { acc[j][0] = 0ull; acc[j][1] = 0ull; }

            #pragma unroll 4
            for (int dd = 0; dd < DD; ++dd) {
                float4 xv = *(const float4*)&xs[dd][tb];
                unsigned long long x01 = pack2(xv.x, xv.y);
                unsigned long long x23 = pack2(xv.z, xv.w);
                #pragma unroll
                for (int j = 0; j < 8; ++j) {
                    float ev = es[kg * 8 + j][dd];
                    unsigned long long ee = pack2(ev, ev);
                    acc[j][0] = ffma2(x01, ee, acc[j][0]);
                    acc[j][1] = ffma2(x23, ee, acc[j][1]);
                }
            }

            // epilogue: dist = (x2 - 2*dot) + e2, running argmin (strict <, k ascending)
            #pragma unroll
            for (int j = 0; j < 8; ++j) {
                int k = c * KC + kg * 8 + j;
                float e2v = __ldg(e2g + k);
                float2 d01 = unpack2(acc[j][0]);
                float2 d23 = unpack2(acc[j][1]);
                float dv0 = (x2[0] - 2.0f * d01.x) + e2v;
                float dv1 = (x2[1] - 2.0f * d01.y) + e2v;
                float dv2 = (x2[2] - 2.0f * d23.x) + e2v;
                float dv3 = (x2[3] - 2.0f * d23.y) + e2v;
                if (dv0 < best[0]) { best[0] = dv0; bidx[0] = k; }
                if (dv1 < best[1]) { best[1] = dv1; bidx[1] = k; }
                if (dv2 < best[2]) { best[2] = dv2; bidx[2] = k; }
                if (dv3 < best[3]) { best[3] = dv3; bidx[3] = k; }
            }
        }
        __syncthreads();
    }

    // ---- cross-thread reduce over the 8 code-slices (overlay on es) ----
    float* rval = &es[0][0];                       // TT*8 floats
    int*   ridx = (int*)(&es[0][0]) + 1024;        // TT*8 ints
    int*   bix  = (int*)(&es[0][0]) + 2048;        // TT ints
    if (active) {
        #pragma unroll
        for (int i = 0; i < 4; ++i) {
            rval[(tb + i) * 8 + kg] = best[i];
            ridx[(tb + i) * 8 + kg] = bidx[i];
        }
    }
    __syncthreads();
    if (tid < TT) {
        float bv = rval[tid * 8];
        int bi = ridx[tid * 8];
        #pragma unroll
        for (int r = 1; r < 8; ++r) {
            float v = rval[tid * 8 + r];
            int ii = ridx[tid * 8 + r];
            if (v < bv || (v == bv && ii < bi)) { bv = v; bi = ii; }
        }
        bix[tid] = bi;
    }
    __syncthreads();

    // ---- gather + write (dd-major rows: coalesced stores) ----
    float* out2 = out + (size_t)BB * CF * TS;
    const size_t obase = ((size_t)(b * CF + g * DD)) * TS + t0;
    for (int i = tid; i < DD * TT; i += NTH) {
        int dd = i / TT, tt = i % TT;
        if (tt < nt) {
            float v = cbg[(size_t)bix[tt] * DD + dd];
            size_t o = obase + (size_t)dd * TS + tt;
            out[o] = v;
            if (two_copies) out2[o] = v;
        }
    }
}

extern "C" void kernel_launch(void* const* d_in, const int* in_sizes, int n_in,
                              void* d_out, int out_size) {
    // identify inputs by size (x: 32768000, codebooks: 524288)
    const float* x  = (const float*)d_in[0];
    const float* cb = (const float*)d_in[1];
    if (n_in >= 2 && in_sizes[0] == GG * KK * DD) {
        x = (const float*)d_in[1];
        cb = (const float*)d_in[0];
    }
    float* out = (float*)d_out;
    int two = (out_size >= 2 * BB * CF * TS) ? 1 : 0;

    e2_kernel<<<(GG * KK + NTH - 1) / NTH, NTH>>>(cb);
    vq_main<<<GG * BB * TILES, NTH>>>(x, cb, out, two);
}

// round 2
// speedup vs baseline: 1.6705x; 1.6705x over previous
#include <cuda_runtime.h>

#define GG   8          // groups
#define KK   1024       // codes per group
#define DD   64         // sub-dim
#define BB   16         // batch
#define TS   4000       // time steps
#define CF   512        // C*F
#define TT   128        // tokens per CTA tile
#define TILES 32        // ceil(4000/128)
#define KC   64         // codes per smem chunk
#define NTH  128

__device__ float g_e2[GG * KK];

// ---- packed f32x2 helpers (Blackwell FFMA2) ----
__device__ __forceinline__ unsigned long long pack2(float x, float y) {
    unsigned long long r;
    asm("mov.b64 %0, {%1, %2};" : "=l"(r) : "f"(x), "f"(y));
    return r;
}
__device__ __forceinline__ unsigned long long ffma2(unsigned long long a,
                                                    unsigned long long b,
                                                    unsigned long long c) {
    unsigned long long d;
    asm("fma.rn.f32x2 %0, %1, %2, %3;" : "=l"(d) : "l"(a), "l"(b), "l"(c));
    return d;
}
__device__ __forceinline__ float2 unpack2(unsigned long long v) {
    float2 r;
    asm("mov.b64 {%0, %1}, %2;" : "=f"(r.x), "=f"(r.y) : "l"(v));
    return r;
}

// e2[g][k] = sum_d cb[g][k][d]^2, deterministic sequential order
__global__ void e2_kernel(const float* __restrict__ cb) {
    int k = blockIdx.x * blockDim.x + threadIdx.x;
    if (k < GG * KK) {
        const float* r = cb + (size_t)k * DD;
        float s = 0.f;
        #pragma unroll
        for (int d = 0; d < DD; ++d) s = fmaf(r[d], r[d], s);
        g_e2[k] = s;
    }
}

__global__ __launch_bounds__(NTH, 4)
void vq_main(const float* __restrict__ x, const float* __restrict__ cb,
             float* __restrict__ out, int two_copies) {
    __shared__ float xs[DD][TT];   // 32 KB, [d][t]
    __shared__ float es[DD][KC];   // 16 KB, [d][k]  (transposed codebook chunk)

    const int tile = blockIdx.x % TILES;
    int rest = blockIdx.x / TILES;
    const int b = rest % BB;
    const int g = rest / BB;
    const int t0 = tile * TT;
    const int nt = min(TT, TS - t0);
    const int tid = threadIdx.x;

    // ---- load x tile (coalesced float4) ----
    const float* xb = x + ((size_t)(b * CF + g * DD)) * TS + t0;
    if (nt == TT) {
        #pragma unroll
        for (int i = tid; i < DD * (TT / 4); i += NTH) {
            int dd = i >> 5, tq = i & 31;
            float4 v = *(const float4*)(xb + (size_t)dd * TS + tq * 4);
            *(float4*)&xs[dd][tq * 4] = v;
        }
    } else {
        for (int i = tid; i < DD * TT; i += NTH) {
            int dd = i / TT, tt = i % TT;
            xs[dd][tt] = (tt < nt) ? xb[(size_t)dd * TS + tt] : 0.f;
        }
    }
    __syncthreads();

    const int kg = tid & 7;          // code-slice 0..7
    const int tb = (tid >> 3) * 8;   // token base, 16 groups * 8 = 128 tokens

    // ---- per-thread x2 for its 8 tokens (sequential d order) ----
    float x2v[8];
    #pragma unroll
    for (int i = 0; i < 8; ++i) x2v[i] = 0.f;
    #pragma unroll 8
    for (int dd = 0; dd < DD; ++dd) {
        float4 a = *(const float4*)&xs[dd][tb];
        float4 c = *(const float4*)&xs[dd][tb + 4];
        x2v[0] = fmaf(a.x, a.x, x2v[0]);
        x2v[1] = fmaf(a.y, a.y, x2v[1]);
        x2v[2] = fmaf(a.z, a.z, x2v[2]);
        x2v[3] = fmaf(a.w, a.w, x2v[3]);
        x2v[4] = fmaf(c.x, c.x, x2v[4]);
        x2v[5] = fmaf(c.y, c.y, x2v[5]);
        x2v[6] = fmaf(c.z, c.z, x2v[6]);
        x2v[7] = fmaf(c.w, c.w, x2v[7]);
    }

    const float* cbg = cb + (size_t)g * KK * DD;
    const float* e2g = g_e2 + g * KK;

    const float INF = __int_as_float(0x7f800000);
    float best[8];
    int bidx[8];
    #pragma unroll
    for (int i = 0; i < 8; ++i) { best[i] = INF; bidx[i] = 0; }

    for (int c = 0; c < KK / KC; ++c) {
        // ---- transpose-load codebook chunk into es[d][k] ----
        {
            const float* src = cbg + (size_t)c * KC * DD;
            int kl = tid >> 1;          // code 0..63
            int p = tid & 1;            // half-row
            #pragma unroll
            for (int q = 0; q < 8; ++q) {
                int d0 = p * 32 + q * 4;
                float4 v = *(const float4*)(src + kl * DD + d0);
                es[d0 + 0][kl] = v.x;
                es[d0 + 1][kl] = v.y;
                es[d0 + 2][kl] = v.z;
                es[d0 + 3][kl] = v.w;
            }
        }
        __syncthreads();

        unsigned long long acc[8][4];
        #pragma unroll
        for (int j = 0; j < 8; ++j)
            #pragma unroll
            for (int p = 0; p < 4; ++p) acc[j][p] = 0ull;

        #pragma unroll 4
        for (int dd = 0; dd < DD; ++dd) {
            float4 xa = *(const float4*)&xs[dd][tb];
            float4 xc = *(const float4*)&xs[dd][tb + 4];
            unsigned long long xp[4];
            xp[0] = pack2(xa.x, xa.y);
            xp[1] = pack2(xa.z, xa.w);
            xp[2] = pack2(xc.x, xc.y);
            xp[3] = pack2(xc.z, xc.w);
            float4 ea = *(const float4*)&es[dd][kg * 8];
            float4 eb = *(const float4*)&es[dd][kg * 8 + 4];
            float ev[8] = {ea.x, ea.y, ea.z, ea.w, eb.x, eb.y, eb.z, eb.w};
            #pragma unroll
            for (int j = 0; j < 8; ++j) {
                unsigned long long ee = pack2(ev[j], ev[j]);
                #pragma unroll
                for (int p = 0; p < 4; ++p)
                    acc[j][p] = ffma2(xp[p], ee, acc[j][p]);
            }
        }

        // ---- epilogue: dist = (x2 - 2*dot) + e2, running argmin ----
        #pragma unroll
        for (int j = 0; j < 8; ++j) {
            int k = c * KC + kg * 8 + j;
            float e2v = __ldg(e2g + k);
            #pragma unroll
            for (int p = 0; p < 4; ++p) {
                float2 dp = unpack2(acc[j][p]);
                float dv0 = fmaf(dp.x, -2.0f, x2v[2 * p]) + e2v;
                float dv1 = fmaf(dp.y, -2.0f, x2v[2 * p + 1]) + e2v;
                if (dv0 < best[2 * p])     { best[2 * p] = dv0;     bidx[2 * p] = k; }
                if (dv1 < best[2 * p + 1]) { best[2 * p + 1] = dv1; bidx[2 * p + 1] = k; }
            }
        }
        __syncthreads();
    }

    // ---- cross-slice reduce (overlay on es) ----
    float* rval = &es[0][0];                 // TT*8 floats (4 KB)
    int*   ridx = (int*)(&es[0][0]) + 1024;  // TT*8 ints  (4 KB)
    int*   bix  = (int*)(&es[0][0]) + 2048;  // TT ints
    #pragma unroll
    for (int i = 0; i < 8; ++i) {
        rval[(tb + i) * 8 + kg] = best[i];
        ridx[(tb + i) * 8 + kg] = bidx[i];
    }
    __syncthreads();
    {
        int t = tid;  // 128 threads = 128 tokens
        float bv = rval[t * 8];
        int bi = ridx[t * 8];
        #pragma unroll
        for (int r = 1; r < 8; ++r) {
            float v = rval[t * 8 + r];
            int ii = ridx[t * 8 + r];
            if (v < bv || (v == bv && ii < bi)) { bv = v; bi = ii; }
        }
        bix[t] = bi;
    }
    __syncthreads();

    // ---- stage gathered code rows through xs (transpose; bank = t mod 32) ----
    {
        int t = tid;
        const float* row = cbg + (size_t)bix[t] * DD;
        #pragma unroll
        for (int q = 0; q < DD / 4; ++q) {
            float4 v = __ldg((const float4*)row + q);
            xs[q * 4 + 0][t] = v.x;
            xs[q * 4 + 1][t] = v.y;
            xs[q * 4 + 2][t] = v.z;
            xs[q * 4 + 3][t] = v.w;
        }
    }
    __syncthreads();

    // ---- coalesced float4 writes (both output copies) ----
    float* out2 = out + (size_t)BB * CF * TS;
    const size_t obase = ((size_t)(b * CF + g * DD)) * TS + t0;
    if (nt == TT) {
        #pragma unroll
        for (int i = tid; i < DD * (TT / 4); i += NTH) {
            int dd = i >> 5, tq = i & 31;
            float4 v = *(const float4*)&xs[dd][tq * 4];
            size_t o = obase + (size_t)dd * TS + tq * 4;
            *(float4*)(out + o) = v;
            if (two_copies) *(float4*)(out2 + o) = v;
        }
    } else {
        for (int i = tid; i < DD * TT; i += NTH) {
            int dd = i / TT, tt = i % TT;
            if (tt < nt) {
                float v = xs[dd][tt];
                size_t o = obase + (size_t)dd * TS + tt;
                out[o] = v;
                if (two_copies) out2[o] = v;
            }
        }
    }
}

extern "C" void kernel_launch(void* const* d_in, const int* in_sizes, int n_in,
                              void* d_out, int out_size) {
    const float* x  = (const float*)d_in[0];
    const float* cb = (const float*)d_in[1];
    if (n_in >= 2 && in_sizes[0] == GG * KK * DD) {
        x = (const float*)d_in[1];
        cb = (const float*)d_in[0];
    }
    float* out = (float*)d_out;
    int two = (out_size >= 2 * BB * CF * TS) ? 1 : 0;

    e2_kernel<<<(GG * KK + NTH - 1) / NTH, NTH>>>(cb);
    vq_main<<<GG * BB * TILES, NTH>>>(x, cb, out, two);
}